// round 14
// baseline (speedup 1.0000x reference)
#include <cuda_runtime.h>
#include <cstdint>

typedef unsigned long long u64;

// fp32 scratch for W_h powers (device-global: allocation-free scratch)
__device__ float g_W2[256 * 256];
__device__ float g_W4[256 * 256];
__device__ float g_W8[256 * 256];
__device__ float g_W16[256 * 256];

// ---------------- f32x2 packed helpers (scan path) ---------------------------
__device__ __forceinline__ u64 ffma2(u64 a, u64 b, u64 c) {
    u64 d;
    asm("fma.rn.f32x2 %0, %1, %2, %3;" : "=l"(d) : "l"(a), "l"(b), "l"(c));
    return d;
}
__device__ __forceinline__ float2 unpack2(u64 v) {
    float2 f;
    asm("mov.b64 {%0, %1}, %2;" : "=f"(f.x), "=f"(f.y) : "l"(v));
    return f;
}
__device__ __forceinline__ float tf32_rn(float x) {
    uint32_t u;
    asm("cvt.rna.tf32.f32 %0, %1;" : "=r"(u) : "f"(x));
    return __uint_as_float(u);
}

// mma.sync m16n8k8 tf32 (baseline PTX, sm_80+; no sm_103a feature needed)
#define MMA_TF32(d, a, b0, b1)                                             \
    asm volatile(                                                          \
        "mma.sync.aligned.m16n8k8.row.col.f32.tf32.tf32.f32 "              \
        "{%0,%1,%2,%3}, {%4,%5,%6,%7}, {%8,%9}, {%0,%1,%2,%3};"            \
        : "+f"((d)[0]), "+f"((d)[1]), "+f"((d)[2]), "+f"((d)[3])           \
        : "r"((a)[0]), "r"((a)[1]), "r"((a)[2]), "r"((a)[3]),              \
          "r"(b0), "r"(b1))

// SMEM float-offsets for mma_gemm tiles ([row][k], stride 20 floats)
#define SM_AHI 0
#define SM_ALO 5120
#define SM_BHI 10240
#define SM_BLO 15360
static constexpr int MMA_SMEM_BYTES = 20480 * 4;   // 81920

// =============================================================================
// Unified tensor-core tf32 3-pass GEMM (ports R10's proven index math).
//   mode 0 (xproj):     out[rr,:]  = X[rr,:] @ Wx^T + bias        (overwrite)
//   mode 1 (corr l):    out[b,t]  += W^(2^(l-1)) @ out[b, t-2^(l-1)]
//   mode 2 (bkfl l):    out[b,t]  += W^(2^l)     @ h[b, t-2^l] (i==0 -> hidden)
// CTA: 128(M) x 128(N) x K=256, 16 double-buffered k-chunks of 16.
// 8 warps, warp tile 32x64 (2x8 m16n8 tiles), 3 passes hi*hi+hi*lo+lo*hi.
// =============================================================================
__global__ __launch_bounds__(256) void mma_gemm(
    const float* __restrict__ X, const float* __restrict__ hidden,
    const float* __restrict__ W, const float* __restrict__ bias,
    float* __restrict__ out, int mode, int level)
{
    extern __shared__ float sm[];
    const int tid  = threadIdx.x;
    const int lane = tid & 31, wid = tid >> 5;
    const int mBase = blockIdx.x * 128, nBase = blockIdx.y * 128;
    const int lrow = tid & 127, lkg0 = tid >> 7;

    // ---- A global row pointer (R10 formulas) ----
    const int rA = mBase + lrow;
    const float* Aptr;
    if (mode == 0) {
        Aptr = X + (size_t)rA * 256;
    } else {
        const int l2 = (mode == 1) ? (11 - level) : (10 - level);
        const int b = rA >> l2, i = rA & ((1 << l2) - 1);
        int s;
        if (mode == 1) s = ((i << level) + (1 << level) - 1) - (1 << (level - 1));
        else           s = ((i << (level + 1)) + (1 << level) - 1) - (1 << level);
        Aptr = (mode == 2 && i == 0) ? hidden + (size_t)b * 256
                                     : out + ((size_t)b * 2048 + s) * 256;
    }

    // ---- B matrix selection ----
    const float* Bmat; int bstr;
    if (mode == 0) { Bmat = W; bstr = 512; }
    else {
        const int mi = (mode == 1) ? (level - 1) : level;   // 0:Wh 1:W2 2:W4 3:W8
        if (mi == 0)      { Bmat = W + 256; bstr = 512; }
        else if (mi == 1) { Bmat = g_W2;    bstr = 256; }
        else if (mi == 2) { Bmat = g_W4;    bstr = 256; }
        else              { Bmat = g_W8;    bstr = 256; }
    }
    const float* Bptr = Bmat + (size_t)(nBase + lrow) * bstr;

    // ---- loaders ----
    float4 fa0, fa1, fb0, fb1;
    auto fetch = [&](int kt) {
        const float* ap = Aptr + kt * 16;
        const float* bp = Bptr + kt * 16;
        fa0 = *(const float4*)(ap + lkg0 * 4);
        fa1 = *(const float4*)(ap + (lkg0 + 2) * 4);
        fb0 = *(const float4*)(bp + lkg0 * 4);
        fb1 = *(const float4*)(bp + (lkg0 + 2) * 4);
    };
    auto split4 = [&](float* hp, float* lp, float4 v) {
        float4 h, l;
        h.x = tf32_rn(v.x); l.x = tf32_rn(v.x - h.x);
        h.y = tf32_rn(v.y); l.y = tf32_rn(v.y - h.y);
        h.z = tf32_rn(v.z); l.z = tf32_rn(v.z - h.z);
        h.w = tf32_rn(v.w); l.w = tf32_rn(v.w - h.w);
        *(float4*)hp = h; *(float4*)lp = l;
    };
    auto stage = [&](int buf) {
        const int ka = lkg0 * 4, kb = ka + 8;
        const int base = lrow * 20 + buf * 2560;
        split4(sm + SM_AHI + base + ka, sm + SM_ALO + base + ka, fa0);
        split4(sm + SM_AHI + base + kb, sm + SM_ALO + base + kb, fa1);
        split4(sm + SM_BHI + base + ka, sm + SM_BLO + base + ka, fb0);
        split4(sm + SM_BHI + base + kb, sm + SM_BLO + base + kb, fb1);
    };

    // ---- accumulators ----
    float acc[2][8][4];
    #pragma unroll
    for (int tm = 0; tm < 2; tm++)
        #pragma unroll
        for (int tn = 0; tn < 8; tn++)
            #pragma unroll
            for (int q = 0; q < 4; q++) acc[tm][tn][q] = 0.f;

    const int wm = (wid & 3) * 32;
    const int wn = (wid >> 2) * 64;
    const int g  = lane >> 2;
    const int c  = lane & 3;

    fetch(0);
    stage(0);
    __syncthreads();

    #pragma unroll 1
    for (int kt = 0; kt < 16; kt++) {
        const int cur = kt & 1;
        if (kt < 15) fetch(kt + 1);

        const uint32_t* Ah = (const uint32_t*)(sm + SM_AHI + cur * 2560);
        const uint32_t* Al = (const uint32_t*)(sm + SM_ALO + cur * 2560);
        const uint32_t* Bh = (const uint32_t*)(sm + SM_BHI + cur * 2560);
        const uint32_t* Bl = (const uint32_t*)(sm + SM_BLO + cur * 2560);

        #pragma unroll
        for (int kk = 0; kk < 16; kk += 8) {
            uint32_t ahi[2][4], alo[2][4];
            #pragma unroll
            for (int tm = 0; tm < 2; tm++) {
                const int o = (wm + tm * 16 + g) * 20 + kk + c;
                ahi[tm][0] = Ah[o];       ahi[tm][1] = Ah[o + 160];
                ahi[tm][2] = Ah[o + 4];   ahi[tm][3] = Ah[o + 164];
                alo[tm][0] = Al[o];       alo[tm][1] = Al[o + 160];
                alo[tm][2] = Al[o + 4];   alo[tm][3] = Al[o + 164];
            }
            #pragma unroll
            for (int tn = 0; tn < 8; tn++) {
                const int ob = (wn + tn * 8 + g) * 20 + kk + c;
                uint32_t bh0 = Bh[ob], bh1 = Bh[ob + 4];
                uint32_t bl0 = Bl[ob], bl1 = Bl[ob + 4];
                MMA_TF32(acc[0][tn], ahi[0], bh0, bh1);
                MMA_TF32(acc[1][tn], ahi[1], bh0, bh1);
                MMA_TF32(acc[0][tn], ahi[0], bl0, bl1);
                MMA_TF32(acc[1][tn], ahi[1], bl0, bl1);
                MMA_TF32(acc[0][tn], alo[0], bh0, bh1);
                MMA_TF32(acc[1][tn], alo[1], bh0, bh1);
            }
        }
        if (kt < 15) stage(cur ^ 1);
        __syncthreads();
    }

    // ---- epilogue (m16n8 D-fragment mapping: rows g/g+8, cols 2c/2c+1) ----
    auto row_ptr = [&](int rr) -> float* {
        if (mode == 0) return out + (size_t)rr * 256;
        const int l2 = (mode == 1) ? (11 - level) : (10 - level);
        const int b = rr >> l2, i = rr & ((1 << l2) - 1);
        const int t = (mode == 1) ? ((i << level) + (1 << level) - 1)
                                  : ((i << (level + 1)) + (1 << level) - 1);
        return out + ((size_t)b * 2048 + t) * 256;
    };

    #pragma unroll
    for (int tm = 0; tm < 2; tm++) {
        const int rr0 = mBase + wm + tm * 16 + g;
        float* o0 = row_ptr(rr0);
        float* o1 = row_ptr(rr0 + 8);
        #pragma unroll
        for (int tn = 0; tn < 8; tn++) {
            const int col = nBase + wn + tn * 8 + 2 * c;
            if (mode == 0) {
                float2 bv = *(const float2*)(bias + col);
                float2 v0 = make_float2(acc[tm][tn][0] + bv.x, acc[tm][tn][1] + bv.y);
                float2 v1 = make_float2(acc[tm][tn][2] + bv.x, acc[tm][tn][3] + bv.y);
                *(float2*)(o0 + col) = v0;
                *(float2*)(o1 + col) = v1;
            } else {
                float2 e0 = *(const float2*)(o0 + col);
                float2 e1 = *(const float2*)(o1 + col);
                e0.x += acc[tm][tn][0]; e0.y += acc[tm][tn][1];
                e1.x += acc[tm][tn][2]; e1.y += acc[tm][tn][3];
                *(float2*)(o0 + col) = e0;
                *(float2*)(o1 + col) = e1;
            }
        }
    }
}

// =============================================================================
// Matrix power kernels (scalar fp32, tiny).
// =============================================================================
__global__ __launch_bounds__(256) void w2_kernel(const float* __restrict__ W)
{
    __shared__ float rowj[256];
    const int j = blockIdx.x, k = threadIdx.x;
    rowj[k] = W[(size_t)j * 512 + 256 + k];
    __syncthreads();
    float acc = 0.f;
    #pragma unroll 8
    for (int m = 0; m < 256; m++)
        acc += rowj[m] * W[(size_t)m * 512 + 256 + k];
    g_W2[j * 256 + k] = acc;
}

__global__ __launch_bounds__(256) void wsq_kernel(int which)
{
    const float* src = (which == 0) ? g_W2 : (which == 1) ? g_W4 : g_W8;
    float*       dst = (which == 0) ? g_W4 : (which == 1) ? g_W8 : g_W16;
    __shared__ float rowj[256];
    const int j = blockIdx.x, k = threadIdx.x;
    rowj[k] = src[j * 256 + k];
    __syncthreads();
    float acc = 0.f;
    #pragma unroll 8
    for (int m = 0; m < 256; m++)
        acc += rowj[m] * src[m * 256 + k];
    dst[j * 256 + k] = acc;
}

// =============================================================================
// Phase 2: W^16 scan, 128 steps (unchanged from R10 — proven fp32 FFMA2 path).
// =============================================================================
__global__ __launch_bounds__(512, 1) void rnn_scan(
    const float* __restrict__ hidden, float* __restrict__ out)
{
    extern __shared__ u64 dynsm[];
    u64*   resw = dynsm;                     // [20][512] u64         (81920 B)
    float* part = (float*)(dynsm + 10240);   // [256*9] floats         (9216 B)
    u64*   h2   = dynsm + 11392;             // [2][8*17] u64 (padded) (2176 B)

    const int tid  = threadIdx.x;
    const int b    = blockIdx.x;
    const int q    = tid & 7;
    const int jset = tid >> 3;

    u64 w[4][11];
    #pragma unroll
    for (int u = 0; u < 4; u++) {
        const u64* wr = (const u64*)(g_W16 + (size_t)(jset * 4 + u) * 256);
        #pragma unroll
        for (int i = 0; i < 11; i++) w[u][i] = wr[q * 16 + i];
        #pragma unroll
        for (int ir = 0; ir < 5; ir++)
            resw[(u * 5 + ir) * 512 + tid] = wr[q * 16 + 11 + ir];
    }

    if (tid < 128) {
        u64 hv = ((const u64*)(hidden + (size_t)b * 256))[tid];
        h2[(tid >> 4) * 17 + (tid & 15)] = hv;
    }

    float xpre = 0.f;
    float* outp = out + (size_t)b * 2048 * 256 + 15 * 256 + tid;
    if (tid < 256) xpre = *outp;

    __syncthreads();

    const u64* rw = resw + tid;

    #pragma unroll 1
    for (int t = 0; t < 128; t++) {
        const u64* hb = h2 + (t & 1) * 136 + q * 17;
        u64 a0 = 0, a1 = 0, a2 = 0, a3 = 0;
        #pragma unroll
        for (int i = 0; i < 11; i++) {
            u64 hh = hb[i];
            a0 = ffma2(w[0][i], hh, a0);
            a1 = ffma2(w[1][i], hh, a1);
            a2 = ffma2(w[2][i], hh, a2);
            a3 = ffma2(w[3][i], hh, a3);
        }
        #pragma unroll
        for (int ir = 0; ir < 5; ir++) {
            u64 hh = hb[11 + ir];
            a0 = ffma2(rw[(0 * 5 + ir) * 512], hh, a0);
            a1 = ffma2(rw[(1 * 5 + ir) * 512], hh, a1);
            a2 = ffma2(rw[(2 * 5 + ir) * 512], hh, a2);
            a3 = ffma2(rw[(3 * 5 + ir) * 512], hh, a3);
        }
        float2 f0 = unpack2(a0), f1 = unpack2(a1), f2 = unpack2(a2), f3 = unpack2(a3);
        const int pb = (jset * 4) * 9 + q;
        part[pb]      = f0.x + f0.y;
        part[pb + 9]  = f1.x + f1.y;
        part[pb + 18] = f2.x + f2.y;
        part[pb + 27] = f3.x + f3.y;
        __syncthreads();
        if (tid < 256) {
            const float* pr = part + tid * 9;
            float s = ((pr[0] + pr[1]) + (pr[2] + pr[3]))
                    + ((pr[4] + pr[5]) + (pr[6] + pr[7]));
            float hnew = s + xpre;
            int p = tid >> 1;
            float* hw = (float*)(h2 + ((t + 1) & 1) * 136);
            hw[((p >> 4) * 17 + (p & 15)) * 2 + (tid & 1)] = hnew;
            *outp = hnew;
            if (t < 127) xpre = outp[4096];
            outp += 4096;
        }
        __syncthreads();
    }
}

// =============================================================================
extern "C" void kernel_launch(void* const* d_in, const int* in_sizes, int n_in,
                              void* d_out, int out_size)
{
    (void)in_sizes; (void)n_in; (void)out_size;
    const float* X      = (const float*)d_in[0];   // input_seq [64,2048,256]
    const float* hidden = (const float*)d_in[1];   // [64,256]
    const float* W      = (const float*)d_in[2];   // [256,512]
    const float* bias   = (const float*)d_in[3];   // [256]
    float* out          = (float*)d_out;           // [64,2048,256]

    cudaFuncSetAttribute(mma_gemm,
        cudaFuncAttributeMaxDynamicSharedMemorySize, MMA_SMEM_BYTES);
    cudaFuncSetAttribute(rnn_scan,
        cudaFuncAttributeMaxDynamicSharedMemorySize, 93312);

    // 1) Wh powers: W2, W4, W8, W16.
    w2_kernel<<<256, 256>>>(W);
    wsq_kernel<<<256, 256>>>(0);
    wsq_kernel<<<256, 256>>>(1);
    wsq_kernel<<<256, 256>>>(2);

    // 2) xproj (tensor cores): out = X @ Wx^T + bias.
    mma_gemm<<<dim3(1024, 2), 256, MMA_SMEM_BYTES>>>(X, hidden, W, bias, out, 0, 0);

    // 3) correction tree, levels 1..4 (B = Wh, W2, W4, W8).
    mma_gemm<<<dim3(512, 2), 256, MMA_SMEM_BYTES>>>(X, hidden, W, bias, out, 1, 1);
    mma_gemm<<<dim3(256, 2), 256, MMA_SMEM_BYTES>>>(X, hidden, W, bias, out, 1, 2);
    mma_gemm<<<dim3(128, 2), 256, MMA_SMEM_BYTES>>>(X, hidden, W, bias, out, 1, 3);
    mma_gemm<<<dim3(64,  2), 256, MMA_SMEM_BYTES>>>(X, hidden, W, bias, out, 1, 4);

    // 4) W^16 scan, 128 steps.
    rnn_scan<<<64, 512, 93312>>>(hidden, out);

    // 5) backfill levels 3..0 (B = W8, W4, W2, Wh).
    mma_gemm<<<dim3(64,  2), 256, MMA_SMEM_BYTES>>>(X, hidden, W, bias, out, 2, 3);
    mma_gemm<<<dim3(128, 2), 256, MMA_SMEM_BYTES>>>(X, hidden, W, bias, out, 2, 2);
    mma_gemm<<<dim3(256, 2), 256, MMA_SMEM_BYTES>>>(X, hidden, W, bias, out, 2, 1);
    mma_gemm<<<dim3(512, 2), 256, MMA_SMEM_BYTES>>>(X, hidden, W, bias, out, 2, 0);
}

// round 15
// speedup vs baseline: 1.5826x; 1.5826x over previous
#include <cuda_runtime.h>
#include <cstdint>

typedef unsigned long long u64;

// fp32 scratch for W_h powers (device-global: allocation-free scratch)
__device__ float g_W2[256 * 256];
__device__ float g_W4[256 * 256];
__device__ float g_W8[256 * 256];
__device__ float g_W16[256 * 256];

// ---------------- f32x2 packed helpers (scan path) ---------------------------
__device__ __forceinline__ u64 ffma2(u64 a, u64 b, u64 c) {
    u64 d;
    asm("fma.rn.f32x2 %0, %1, %2, %3;" : "=l"(d) : "l"(a), "l"(b), "l"(c));
    return d;
}
__device__ __forceinline__ float2 unpack2(u64 v) {
    float2 f;
    asm("mov.b64 {%0, %1}, %2;" : "=f"(f.x), "=f"(f.y) : "l"(v));
    return f;
}

// pack two fp32 -> bf16x2 (x0 in low half = even k, x1 in high half)
__device__ __forceinline__ uint32_t packbf(float x0, float x1) {
    uint32_t r;
    asm("cvt.rn.bf16x2.f32 %0, %1, %2;" : "=r"(r) : "f"(x1), "f"(x0));
    return r;
}

// mma.sync m16n8k16 bf16 (baseline PTX, sm_80+)
#define MMA_BF16(d, a, b0, b1)                                             \
    asm volatile(                                                          \
        "mma.sync.aligned.m16n8k16.row.col.f32.bf16.bf16.f32 "             \
        "{%0,%1,%2,%3}, {%4,%5,%6,%7}, {%8,%9}, {%0,%1,%2,%3};"            \
        : "+f"((d)[0]), "+f"((d)[1]), "+f"((d)[2]), "+f"((d)[3])           \
        : "r"((a)[0]), "r"((a)[1]), "r"((a)[2]), "r"((a)[3]),              \
          "r"(b0), "r"(b1))

// SMEM u32-offsets for mma_gemm tiles ([row][k-pairs], row stride 12 u32:
// 8 used + 4 pad -> banks (12g+c) mod 32 all-distinct => conflict-free)
#define SM_AHI 0
#define SM_ALO 3072
#define SM_BHI 6144
#define SM_BLO 9216
static constexpr int MMA_SMEM_BYTES = 12288 * 4;   // 49152

// =============================================================================
// Unified tensor-core bf16 3-pass GEMM (index math carried from passing R14).
//   mode 0 (xproj):     out[rr,:]  = X[rr,:] @ Wx^T + bias        (overwrite)
//   mode 1 (corr l):    out[b,t]  += W^(2^(l-1)) @ out[b, t-2^(l-1)]
//   mode 2 (bkfl l):    out[b,t]  += W^(2^l)     @ h[b, t-2^l] (i==0 -> hidden)
// CTA: 128(M) x 128(N) x K=256, 16 double-buffered k-chunks of 16.
// 8 warps, warp tile 32x64 (2x8 m16n8 tiles), passes hi*hi + hi*lo + lo*hi.
// =============================================================================
__global__ __launch_bounds__(256) void mma_gemm(
    const float* __restrict__ X, const float* __restrict__ hidden,
    const float* __restrict__ W, const float* __restrict__ bias,
    float* __restrict__ out, int mode, int level)
{
    extern __shared__ uint32_t smu[];
    const int tid  = threadIdx.x;
    const int lane = tid & 31, wid = tid >> 5;
    const int mBase = blockIdx.x * 128, nBase = blockIdx.y * 128;
    const int lrow = tid & 127, lkg0 = tid >> 7;

    // ---- A global row pointer (R10/R14 formulas) ----
    const int rA = mBase + lrow;
    const float* Aptr;
    if (mode == 0) {
        Aptr = X + (size_t)rA * 256;
    } else {
        const int l2 = (mode == 1) ? (11 - level) : (10 - level);
        const int b = rA >> l2, i = rA & ((1 << l2) - 1);
        int s;
        if (mode == 1) s = ((i << level) + (1 << level) - 1) - (1 << (level - 1));
        else           s = ((i << (level + 1)) + (1 << level) - 1) - (1 << level);
        Aptr = (mode == 2 && i == 0) ? hidden + (size_t)b * 256
                                     : out + ((size_t)b * 2048 + s) * 256;
    }

    // ---- B matrix selection ----
    const float* Bmat; int bstr;
    if (mode == 0) { Bmat = W; bstr = 512; }
    else {
        const int mi = (mode == 1) ? (level - 1) : level;   // 0:Wh 1:W2 2:W4 3:W8
        if (mi == 0)      { Bmat = W + 256; bstr = 512; }
        else if (mi == 1) { Bmat = g_W2;    bstr = 256; }
        else if (mi == 2) { Bmat = g_W4;    bstr = 256; }
        else              { Bmat = g_W8;    bstr = 256; }
    }
    const float* Bptr = Bmat + (size_t)(nBase + lrow) * bstr;

    // ---- loaders: thread covers 8 contiguous k (lkg0 selects half) ----
    float4 fa0, fa1, fb0, fb1;
    auto fetch = [&](int kt) {
        const float* ap = Aptr + kt * 16 + lkg0 * 8;
        const float* bp = Bptr + kt * 16 + lkg0 * 8;
        fa0 = *(const float4*)(ap);
        fa1 = *(const float4*)(ap + 4);
        fb0 = *(const float4*)(bp);
        fb1 = *(const float4*)(bp + 4);
    };
    // split one fp32 pair into bf16x2 hi + bf16x2 lo (exact residual)
    auto split2 = [&](float x0, float x1, uint32_t& hi, uint32_t& lo) {
        hi = packbf(x0, x1);
        float r0 = x0 - __uint_as_float(hi << 16);
        float r1 = x1 - __uint_as_float(hi & 0xffff0000u);
        lo = packbf(r0, r1);
    };
    auto stage = [&](int buf) {
        const int base = lrow * 12 + lkg0 * 4 + buf * 1536;
        uint32_t h[4], l[4];
        split2(fa0.x, fa0.y, h[0], l[0]);
        split2(fa0.z, fa0.w, h[1], l[1]);
        split2(fa1.x, fa1.y, h[2], l[2]);
        split2(fa1.z, fa1.w, h[3], l[3]);
        *(uint4*)(smu + SM_AHI + base) = make_uint4(h[0], h[1], h[2], h[3]);
        *(uint4*)(smu + SM_ALO + base) = make_uint4(l[0], l[1], l[2], l[3]);
        split2(fb0.x, fb0.y, h[0], l[0]);
        split2(fb0.z, fb0.w, h[1], l[1]);
        split2(fb1.x, fb1.y, h[2], l[2]);
        split2(fb1.z, fb1.w, h[3], l[3]);
        *(uint4*)(smu + SM_BHI + base) = make_uint4(h[0], h[1], h[2], h[3]);
        *(uint4*)(smu + SM_BLO + base) = make_uint4(l[0], l[1], l[2], l[3]);
    };

    // ---- accumulators ----
    float acc[2][8][4];
    #pragma unroll
    for (int tm = 0; tm < 2; tm++)
        #pragma unroll
        for (int tn = 0; tn < 8; tn++)
            #pragma unroll
            for (int q = 0; q < 4; q++) acc[tm][tn][q] = 0.f;

    const int wm = (wid & 3) * 32;
    const int wn = (wid >> 2) * 64;
    const int g  = lane >> 2;
    const int c  = lane & 3;

    fetch(0);
    stage(0);
    __syncthreads();

    #pragma unroll 1
    for (int kt = 0; kt < 16; kt++) {
        const int cur = kt & 1;
        if (kt < 15) fetch(kt + 1);

        const uint32_t* Ah = smu + SM_AHI + cur * 1536;
        const uint32_t* Al = smu + SM_ALO + cur * 1536;
        const uint32_t* Bh = smu + SM_BHI + cur * 1536;
        const uint32_t* Bl = smu + SM_BLO + cur * 1536;

        // A fragments: a0=(g, k2c) a1=(g+8, k2c) a2=(g, k8+2c) a3=(g+8, k8+2c)
        uint32_t ah[2][4], al[2][4];
        #pragma unroll
        for (int tm = 0; tm < 2; tm++) {
            const int o0 = (wm + tm * 16 + g) * 12 + c;
            const int o1 = o0 + 96;                      // row +8
            ah[tm][0] = Ah[o0];     ah[tm][1] = Ah[o1];
            ah[tm][2] = Ah[o0 + 4]; ah[tm][3] = Ah[o1 + 4];
            al[tm][0] = Al[o0];     al[tm][1] = Al[o1];
            al[tm][2] = Al[o0 + 4]; al[tm][3] = Al[o1 + 4];
        }
        #pragma unroll
        for (int tn = 0; tn < 8; tn++) {
            const int ob = (wn + tn * 8 + g) * 12 + c;
            uint32_t bh0 = Bh[ob], bh1 = Bh[ob + 4];
            uint32_t bl0 = Bl[ob], bl1 = Bl[ob + 4];
            MMA_BF16(acc[0][tn], ah[0], bh0, bh1);
            MMA_BF16(acc[1][tn], ah[1], bh0, bh1);
            MMA_BF16(acc[0][tn], ah[0], bl0, bl1);
            MMA_BF16(acc[1][tn], ah[1], bl0, bl1);
            MMA_BF16(acc[0][tn], al[0], bh0, bh1);
            MMA_BF16(acc[1][tn], al[1], bh0, bh1);
        }
        if (kt < 15) stage(cur ^ 1);
        __syncthreads();
    }

    // ---- epilogue (m16n8 D mapping: rows g/g+8, cols 2c/2c+1; from R14) ----
    auto row_ptr = [&](int rr) -> float* {
        if (mode == 0) return out + (size_t)rr * 256;
        const int l2 = (mode == 1) ? (11 - level) : (10 - level);
        const int b = rr >> l2, i = rr & ((1 << l2) - 1);
        const int t = (mode == 1) ? ((i << level) + (1 << level) - 1)
                                  : ((i << (level + 1)) + (1 << level) - 1);
        return out + ((size_t)b * 2048 + t) * 256;
    };

    #pragma unroll
    for (int tm = 0; tm < 2; tm++) {
        const int rr0 = mBase + wm + tm * 16 + g;
        float* o0 = row_ptr(rr0);
        float* o1 = row_ptr(rr0 + 8);
        #pragma unroll
        for (int tn = 0; tn < 8; tn++) {
            const int col = nBase + wn + tn * 8 + 2 * c;
            if (mode == 0) {
                float2 bv = *(const float2*)(bias + col);
                float2 v0 = make_float2(acc[tm][tn][0] + bv.x, acc[tm][tn][1] + bv.y);
                float2 v1 = make_float2(acc[tm][tn][2] + bv.x, acc[tm][tn][3] + bv.y);
                *(float2*)(o0 + col) = v0;
                *(float2*)(o1 + col) = v1;
            } else {
                float2 e0 = *(const float2*)(o0 + col);
                float2 e1 = *(const float2*)(o1 + col);
                e0.x += acc[tm][tn][0]; e0.y += acc[tm][tn][1];
                e1.x += acc[tm][tn][2]; e1.y += acc[tm][tn][3];
                *(float2*)(o0 + col) = e0;
                *(float2*)(o1 + col) = e1;
            }
        }
    }
}

// =============================================================================
// Matrix power kernels (scalar fp32, tiny).
// =============================================================================
__global__ __launch_bounds__(256) void w2_kernel(const float* __restrict__ W)
{
    __shared__ float rowj[256];
    const int j = blockIdx.x, k = threadIdx.x;
    rowj[k] = W[(size_t)j * 512 + 256 + k];
    __syncthreads();
    float acc = 0.f;
    #pragma unroll 8
    for (int m = 0; m < 256; m++)
        acc += rowj[m] * W[(size_t)m * 512 + 256 + k];
    g_W2[j * 256 + k] = acc;
}

__global__ __launch_bounds__(256) void wsq_kernel(int which)
{
    const float* src = (which == 0) ? g_W2 : (which == 1) ? g_W4 : g_W8;
    float*       dst = (which == 0) ? g_W4 : (which == 1) ? g_W8 : g_W16;
    __shared__ float rowj[256];
    const int j = blockIdx.x, k = threadIdx.x;
    rowj[k] = src[j * 256 + k];
    __syncthreads();
    float acc = 0.f;
    #pragma unroll 8
    for (int m = 0; m < 256; m++)
        acc += rowj[m] * src[m * 256 + k];
    dst[j * 256 + k] = acc;
}

// =============================================================================
// Phase 2: W^16 scan, 128 steps (unchanged — proven fp32 FFMA2 path).
// =============================================================================
__global__ __launch_bounds__(512, 1) void rnn_scan(
    const float* __restrict__ hidden, float* __restrict__ out)
{
    extern __shared__ u64 dynsm[];
    u64*   resw = dynsm;                     // [20][512] u64         (81920 B)
    float* part = (float*)(dynsm + 10240);   // [256*9] floats         (9216 B)
    u64*   h2   = dynsm + 11392;             // [2][8*17] u64 (padded) (2176 B)

    const int tid  = threadIdx.x;
    const int b    = blockIdx.x;
    const int q    = tid & 7;
    const int jset = tid >> 3;

    u64 w[4][11];
    #pragma unroll
    for (int u = 0; u < 4; u++) {
        const u64* wr = (const u64*)(g_W16 + (size_t)(jset * 4 + u) * 256);
        #pragma unroll
        for (int i = 0; i < 11; i++) w[u][i] = wr[q * 16 + i];
        #pragma unroll
        for (int ir = 0; ir < 5; ir++)
            resw[(u * 5 + ir) * 512 + tid] = wr[q * 16 + 11 + ir];
    }

    if (tid < 128) {
        u64 hv = ((const u64*)(hidden + (size_t)b * 256))[tid];
        h2[(tid >> 4) * 17 + (tid & 15)] = hv;
    }

    float xpre = 0.f;
    float* outp = out + (size_t)b * 2048 * 256 + 15 * 256 + tid;
    if (tid < 256) xpre = *outp;

    __syncthreads();

    const u64* rw = resw + tid;

    #pragma unroll 1
    for (int t = 0; t < 128; t++) {
        const u64* hb = h2 + (t & 1) * 136 + q * 17;
        u64 a0 = 0, a1 = 0, a2 = 0, a3 = 0;
        #pragma unroll
        for (int i = 0; i < 11; i++) {
            u64 hh = hb[i];
            a0 = ffma2(w[0][i], hh, a0);
            a1 = ffma2(w[1][i], hh, a1);
            a2 = ffma2(w[2][i], hh, a2);
            a3 = ffma2(w[3][i], hh, a3);
        }
        #pragma unroll
        for (int ir = 0; ir < 5; ir++) {
            u64 hh = hb[11 + ir];
            a0 = ffma2(rw[(0 * 5 + ir) * 512], hh, a0);
            a1 = ffma2(rw[(1 * 5 + ir) * 512], hh, a1);
            a2 = ffma2(rw[(2 * 5 + ir) * 512], hh, a2);
            a3 = ffma2(rw[(3 * 5 + ir) * 512], hh, a3);
        }
        float2 f0 = unpack2(a0), f1 = unpack2(a1), f2 = unpack2(a2), f3 = unpack2(a3);
        const int pb = (jset * 4) * 9 + q;
        part[pb]      = f0.x + f0.y;
        part[pb + 9]  = f1.x + f1.y;
        part[pb + 18] = f2.x + f2.y;
        part[pb + 27] = f3.x + f3.y;
        __syncthreads();
        if (tid < 256) {
            const float* pr = part + tid * 9;
            float s = ((pr[0] + pr[1]) + (pr[2] + pr[3]))
                    + ((pr[4] + pr[5]) + (pr[6] + pr[7]));
            float hnew = s + xpre;
            int p = tid >> 1;
            float* hw = (float*)(h2 + ((t + 1) & 1) * 136);
            hw[((p >> 4) * 17 + (p & 15)) * 2 + (tid & 1)] = hnew;
            *outp = hnew;
            if (t < 127) xpre = outp[4096];
            outp += 4096;
        }
        __syncthreads();
    }
}

// =============================================================================
extern "C" void kernel_launch(void* const* d_in, const int* in_sizes, int n_in,
                              void* d_out, int out_size)
{
    (void)in_sizes; (void)n_in; (void)out_size;
    const float* X      = (const float*)d_in[0];   // input_seq [64,2048,256]
    const float* hidden = (const float*)d_in[1];   // [64,256]
    const float* W      = (const float*)d_in[2];   // [256,512]
    const float* bias   = (const float*)d_in[3];   // [256]
    float* out          = (float*)d_out;           // [64,2048,256]

    cudaFuncSetAttribute(mma_gemm,
        cudaFuncAttributeMaxDynamicSharedMemorySize, MMA_SMEM_BYTES);
    cudaFuncSetAttribute(rnn_scan,
        cudaFuncAttributeMaxDynamicSharedMemorySize, 93312);

    // 1) Wh powers: W2, W4, W8, W16.
    w2_kernel<<<256, 256>>>(W);
    wsq_kernel<<<256, 256>>>(0);
    wsq_kernel<<<256, 256>>>(1);
    wsq_kernel<<<256, 256>>>(2);

    // 2) xproj (tensor cores): out = X @ Wx^T + bias.
    mma_gemm<<<dim3(1024, 2), 256, MMA_SMEM_BYTES>>>(X, hidden, W, bias, out, 0, 0);

    // 3) correction tree, levels 1..4 (B = Wh, W2, W4, W8).
    mma_gemm<<<dim3(512, 2), 256, MMA_SMEM_BYTES>>>(X, hidden, W, bias, out, 1, 1);
    mma_gemm<<<dim3(256, 2), 256, MMA_SMEM_BYTES>>>(X, hidden, W, bias, out, 1, 2);
    mma_gemm<<<dim3(128, 2), 256, MMA_SMEM_BYTES>>>(X, hidden, W, bias, out, 1, 3);
    mma_gemm<<<dim3(64,  2), 256, MMA_SMEM_BYTES>>>(X, hidden, W, bias, out, 1, 4);

    // 4) W^16 scan, 128 steps.
    rnn_scan<<<64, 512, 93312>>>(hidden, out);

    // 5) backfill levels 3..0 (B = W8, W4, W2, Wh).
    mma_gemm<<<dim3(64,  2), 256, MMA_SMEM_BYTES>>>(X, hidden, W, bias, out, 2, 3);
    mma_gemm<<<dim3(128, 2), 256, MMA_SMEM_BYTES>>>(X, hidden, W, bias, out, 2, 2);
    mma_gemm<<<dim3(256, 2), 256, MMA_SMEM_BYTES>>>(X, hidden, W, bias, out, 2, 1);
    mma_gemm<<<dim3(512, 2), 256, MMA_SMEM_BYTES>>>(X, hidden, W, bias, out, 2, 0);
}